// round 14
// baseline (speedup 1.0000x reference)
#include <cuda_runtime.h>
#include <cuda_fp16.h>
#include <cstdint>

// Problem: b=4, c=256, h=w=64 -> n=4096, GROUPS=8, HEADS=4, head_dim=64
// bh = b*4+head in [0,16)

// ---------------------------------------------------------------------------
// Scratch (__device__ globals; no allocation allowed)
// ---------------------------------------------------------------------------
__device__ __half g_xh[(size_t)4 * 256 * 4096];   // normalized x, fp16 [b*256+c][n]
__device__ __half g_wqh[768 * 256];               // qkv_w fp16
__device__ __half g_pwh[256 * 256];               // proj_w fp16 hi
__device__ __half g_pwl[256 * 256];               // proj_w fp16 lo
__device__ __half g_q[(size_t)16 * 4096 * 64];    // [bh][n][d], pre-scaled 0.125*log2e
__device__ __half g_k[(size_t)16 * 4096 * 64];    // [bh][n][d]
__device__ __half g_v[(size_t)16 * 4096 * 64];    // [bh][n][d]
__device__ __half g_ath[(size_t)4 * 4096 * 256];  // attention out fp16 [b][n][c]
__device__ float g_sA[1024];
__device__ float g_sB[1024];

// ---------------------------------------------------------------------------
// PTX helpers (baseline sm_80+ features only)
// ---------------------------------------------------------------------------
__device__ __forceinline__ uint32_t smem_to_u32(const void* p) {
    uint32_t a;
    asm("{ .reg .u64 t; cvta.to.shared.u64 t, %1; cvt.u32.u64 %0, t; }" : "=r"(a) : "l"(p));
    return a;
}
#define LDSM4(r0, r1, r2, r3, addr) \
    asm volatile("ldmatrix.sync.aligned.m8n8.x4.shared.b16 {%0,%1,%2,%3}, [%4];" \
        : "=r"(r0), "=r"(r1), "=r"(r2), "=r"(r3) : "r"(addr))
#define LDSM4T(r0, r1, r2, r3, addr) \
    asm volatile("ldmatrix.sync.aligned.m8n8.x4.trans.shared.b16 {%0,%1,%2,%3}, [%4];" \
        : "=r"(r0), "=r"(r1), "=r"(r2), "=r"(r3) : "r"(addr))
#define MMAF16(c, a0, a1, a2, a3, b0, b1) \
    asm volatile("mma.sync.aligned.m16n8k16.row.col.f32.f16.f16.f32 " \
        "{%0,%1,%2,%3}, {%4,%5,%6,%7}, {%8,%9}, {%0,%1,%2,%3};" \
        : "+f"((c)[0]), "+f"((c)[1]), "+f"((c)[2]), "+f"((c)[3]) \
        : "r"(a0), "r"(a1), "r"(a2), "r"(a3), "r"(b0), "r"(b1))
#define CP_COMMIT() asm volatile("cp.async.commit_group;" ::: "memory")
#define CP_WAIT(n)  asm volatile("cp.async.wait_group %0;" :: "n"(n) : "memory")

__device__ __forceinline__ uint32_t packh2(float a, float b) {
    __half2 h = __floats2half2_rn(a, b);
    return *(uint32_t*)&h;
}

// cp.async one [64 rows][128B] tile into swizzled SMEM; 128 participating
// threads (ht in 0..127); gmem row pitch in bytes
__device__ __forceinline__ void cpa_tile(uint32_t dst, const char* src, int pitch, int ht) {
    int j = ht >> 1, g0 = (ht & 1) << 2;
    const char* s = src + (size_t)j * pitch + g0 * 16;
#pragma unroll
    for (int r = 0; r < 4; r++) {
        int g = g0 + r;
        uint32_t d = dst + j * 128 + ((g ^ (j & 7)) << 4);
        asm volatile("cp.async.cg.shared.global [%0], [%1], 16;" :: "r"(d), "l"(s + r * 16));
    }
}

// ---------------------------------------------------------------------------
// Kernel 1: GroupNorm statistics + weight conversion (merged).
// blocks [0,32): GN stats -> per-(b,c) affine; blocks [32,1056): wconv.
// ---------------------------------------------------------------------------
__global__ __launch_bounds__(256) void gn_stats_wconv_kernel(
    const float* __restrict__ x, const float* __restrict__ gw,
    const float* __restrict__ gb, const float* __restrict__ qkv_w,
    const float* __restrict__ proj_w) {
    if (blockIdx.x >= 32) {
        int i = (blockIdx.x - 32) * 256 + threadIdx.x;
        if (i < 196608) g_wqh[i] = __float2half_rn(qkv_w[i]);
        int j = i - 196608;
        if (j >= 0 && j < 65536) {
            float v = proj_w[j];
            __half h = __float2half_rn(v);
            g_pwh[j] = h;
            g_pwl[j] = __float2half_rn(v - __half2float(h));
        }
        return;
    }
    int b = blockIdx.x >> 3, g = blockIdx.x & 7;
    const float4* xp = (const float4*)(x + (size_t)(b * 256 + g * 32) * 4096);
    float s = 0.f, s2 = 0.f;
    for (int i = threadIdx.x; i < 32768; i += 256) {
        float4 v = xp[i];
        s  += v.x + v.y + v.z + v.w;
        s2 += v.x * v.x + v.y * v.y + v.z * v.z + v.w * v.w;
    }
#pragma unroll
    for (int o = 16; o; o >>= 1) {
        s  += __shfl_xor_sync(~0u, s, o);
        s2 += __shfl_xor_sync(~0u, s2, o);
    }
    __shared__ float ss[8], ss2[8], stat[2];
    int w = threadIdx.x >> 5;
    if ((threadIdx.x & 31) == 0) { ss[w] = s; ss2[w] = s2; }
    __syncthreads();
    if (threadIdx.x == 0) {
        float t = 0.f, t2 = 0.f;
        for (int k = 0; k < 8; k++) { t += ss[k]; t2 += ss2[k]; }
        float mean = t * (1.f / 131072.f);
        float var  = t2 * (1.f / 131072.f) - mean * mean;
        stat[0] = mean;
        stat[1] = rsqrtf(var + 1e-5f);
    }
    __syncthreads();
    if (threadIdx.x < 32) {
        int c = g * 32 + threadIdx.x;
        float wv = gw[c];
        g_sA[b * 256 + c] = wv * stat[1];
        g_sB[b * 256 + c] = gb[c] - stat[0] * wv * stat[1];
    }
}

// ---------------------------------------------------------------------------
// Kernel 1b: apply GN affine, write fp16 xn [b*256+c][n]
// ---------------------------------------------------------------------------
__global__ __launch_bounds__(128) void gn_apply_kernel(const float* __restrict__ x) {
    int row = blockIdx.x;
    float a = g_sA[row], sh = g_sB[row];
    const float4* xr = (const float4*)(x + (size_t)row * 4096);
    uint2* dst = (uint2*)(g_xh + (size_t)row * 4096);
    for (int i = threadIdx.x; i < 1024; i += 128) {
        float4 v = xr[i];
        uint2 p;
        p.x = packh2(fmaf(v.x, a, sh), fmaf(v.y, a, sh));
        p.y = packh2(fmaf(v.z, a, sh), fmaf(v.w, a, sh));
        dst[i] = p;
    }
}

// ---------------------------------------------------------------------------
// Kernel 2: QKV GEMM via HMMA (single-pass fp16), 2-stage cp.async pipeline.
// out[n 64][o 64] per CTA; A = xn^T (ldmatrix.trans on [c][n] tiles),
// B = qkv_w [o][c]. B-fragment LDSMs batched ahead of MMAs per jo.
// Epilogue: bias + (q scale) -> fp16 [bh][n][d].
// grid (12 o-tiles, 64 n-tiles, 4 b), 128 threads = 4 warps (warp: 16 n rows).
// ---------------------------------------------------------------------------
__global__ __launch_bounds__(128) void gemm_qkv_hmma(const float* __restrict__ bias) {
    __shared__ __align__(128) char sX[2][8192];  // [64 c][64 n] fp16 swizzled
    __shared__ __align__(128) char sW[2][8192];  // [64 o][64 c] fp16 swizzled
    int tid = threadIdx.x, lane = tid & 31, w = tid >> 5;
    int b = blockIdx.z, o0 = blockIdx.x << 6, n0 = blockIdx.y << 6;
    uint32_t uX[2] = {smem_to_u32(sX[0]), smem_to_u32(sX[1])};
    uint32_t uW[2] = {smem_to_u32(sW[0]), smem_to_u32(sW[1])};
    const char* xp = (const char*)g_xh + ((size_t)(b * 256) * 4096 + n0) * 2;
    const char* wp = (const char*)g_wqh + ((size_t)o0 * 256) * 2;

    float cfr[8][4];
#pragma unroll
    for (int t = 0; t < 8; t++)
#pragma unroll
        for (int e = 0; e < 4; e++) cfr[t][e] = 0.f;

    cpa_tile(uX[0], xp, 8192, tid);
    cpa_tile(uW[0], wp, 512, tid);
    CP_COMMIT();

    for (int ci = 0; ci < 4; ci++) {
        int st = ci & 1;
        if (ci < 3) {
            cpa_tile(uX[st ^ 1], xp + (size_t)(ci + 1) * 64 * 8192, 8192, tid);
            cpa_tile(uW[st ^ 1], wp + (ci + 1) * 128, 512, tid);
            CP_COMMIT();
            CP_WAIT(1);
        } else {
            CP_WAIT(0);
        }
        __syncthreads();

        // A fragments (rows = n, K = c) via trans loads, batched
        uint32_t af[4][4];
#pragma unroll
        for (int ks = 0; ks < 4; ks++) {
            int crow = (ks << 4) + ((lane >> 4) << 3) + (lane & 7);
            int g = (w << 1) + ((lane >> 3) & 1);
            LDSM4T(af[ks][0], af[ks][1], af[ks][2], af[ks][3],
                   uX[st] + crow * 128 + ((g ^ (crow & 7)) << 4));
        }
        // B fragments: batch 4 LDSMs per jo, then 8 MMAs
#pragma unroll
        for (int jo = 0; jo < 4; jo++) {
            int orow = (jo << 4) + ((lane >> 4) << 3) + (lane & 7);
            int ors = orow * 128, orx = orow & 7;
            uint32_t bf[4][4];
#pragma unroll
            for (int ks = 0; ks < 4; ks++) {
                int gr = (ks << 1) + ((lane >> 3) & 1);
                LDSM4(bf[ks][0], bf[ks][1], bf[ks][2], bf[ks][3],
                      uW[st] + ors + ((gr ^ orx) << 4));
            }
#pragma unroll
            for (int ks = 0; ks < 4; ks++) {
                MMAF16(cfr[jo * 2],     af[ks][0], af[ks][1], af[ks][2], af[ks][3],
                       bf[ks][0], bf[ks][1]);
                MMAF16(cfr[jo * 2 + 1], af[ks][0], af[ks][1], af[ks][2], af[ks][3],
                       bf[ks][2], bf[ks][3]);
            }
        }
        __syncthreads();
    }

    // epilogue: o tile = one head of one section
    int sect = o0 >> 8;                 // 0=q 1=k 2=v
    int bh = b * 4 + ((o0 >> 6) & 3);
    float scale = (sect == 0) ? 0.18033688f : 1.0f;  // 0.125 * log2(e)
    __half* dst = (sect == 0) ? g_q : ((sect == 1) ? g_k : g_v);
    int r = (w << 4) + (lane >> 2), cx = (lane & 3) << 1;
    size_t rowA = ((size_t)bh * 4096 + n0 + r) * 64;
    size_t rowB = rowA + 8 * 64;
#pragma unroll
    for (int jo = 0; jo < 4; jo++)
#pragma unroll
        for (int blk = 0; blk < 2; blk++) {
            int t = jo * 2 + blk;
            int d0 = (jo << 4) + (blk << 3) + cx;
            float b0f = bias[o0 + d0], b1f = bias[o0 + d0 + 1];
            *(uint32_t*)&dst[rowA + d0] =
                packh2((cfr[t][0] + b0f) * scale, (cfr[t][1] + b1f) * scale);
            *(uint32_t*)&dst[rowB + d0] =
                packh2((cfr[t][2] + b0f) * scale, (cfr[t][3] + b1f) * scale);
        }
}

// ---------------------------------------------------------------------------
// Kernel 3: flash attention via warp mma.sync (fp16 in, f32 accum).
// grid (32 i-tiles of 128 queries, 16 bh), 256 threads = 8 warps; warp w owns
// query rows w*16..+15. Threads 0-127 stream K, 128-255 stream V.
// 3-stage cp.async ring, ONE __syncthreads per 64-key chunk (wait -> barrier
// -> prefetch it+2 -> compute); K-LDSMs batched (4 per jg) ahead of MMAs.
// Max-free softmax (fixed C=6 shift in exp2 domain, cancels in O/l); l via
// persistent ones-column MMA. reg cap 128 via (256,2).
// Output: fp16 att [b][n][256].
// ---------------------------------------------------------------------------
__global__ __launch_bounds__(256, 2) void flash_mma_kernel() {
    __shared__ __align__(128) char sK[3][8192];
    __shared__ __align__(128) char sV[3][8192];
    int tid = threadIdx.x, lane = tid & 31, w = tid >> 5;
    int half = tid >> 7, ht = tid & 127;
    int bh = blockIdx.y, b = bh >> 2, hd = bh & 3;
    int i0 = blockIdx.x << 7;

    uint32_t uK[3] = {smem_to_u32(sK[0]), smem_to_u32(sK[1]), smem_to_u32(sK[2])};
    uint32_t uV[3] = {smem_to_u32(sV[0]), smem_to_u32(sV[1]), smem_to_u32(sV[2])};
    const char* qp = (const char*)g_q + ((size_t)bh * 4096 + i0) * 128;
    const char* kp = (const char*)g_k + ((size_t)bh * 4096) * 128;
    const char* vp = (const char*)g_v + ((size_t)bh * 4096) * 128;

    // ---- stage Q (128 rows): half 0 -> sK[0] rows 0-63, half 1 -> sK[1] ----
    cpa_tile(uK[half], qp + (size_t)half * 64 * 128, 128, ht);
    CP_COMMIT();
    CP_WAIT(0);
    __syncthreads();
    uint32_t qf[4][4];
    {
        int qbuf = w >> 2;
        int row = ((w << 4) & 63) + (lane & 15);
        int rs = row * 128, rx = (row & 7);
#pragma unroll
        for (int ks = 0; ks < 4; ks++) {
            int gr = (ks << 1) + (lane >> 4);
            LDSM4(qf[ks][0], qf[ks][1], qf[ks][2], qf[ks][3],
                  uK[qbuf] + rs + ((gr ^ rx) << 4));
        }
    }
    __syncthreads();  // all reads of sK done before chunk prefetch

    // ---- prefetch chunks 0,1 into stages 0,1 (half 0: K, half 1: V) ----
    if (half == 0) cpa_tile(uK[0], kp, 128, ht);
    else           cpa_tile(uV[0], vp, 128, ht);
    CP_COMMIT();
    if (half == 0) cpa_tile(uK[1], kp + (size_t)64 * 128, 128, ht);
    else           cpa_tile(uV[1], vp + (size_t)64 * 128, 128, ht);
    CP_COMMIT();

    float ofr[8][4];
#pragma unroll
    for (int dt = 0; dt < 8; dt++)
#pragma unroll
        for (int e = 0; e < 4; e++) ofr[dt][e] = 0.f;
    float lfr[4] = {0.f, 0.f, 0.f, 0.f};
    const uint32_t ONESH2 = 0x3C003C00u;  // half2(1,1)
    const float CSH = 6.0f;               // fixed exp2-domain shift

    for (int it = 0; it < 64; it++) {
        // chunk `it` complete (2 groups outstanding normally)
        if (it < 63) CP_WAIT(1);
        else         CP_WAIT(0);
        __syncthreads();  // visibility + stage (it+2)%3's prior readers done
        if (it + 2 < 64) {
            int ps = (it + 2) % 3;
            if (half == 0) cpa_tile(uK[ps], kp + (size_t)(it + 2) * 64 * 128, 128, ht);
            else           cpa_tile(uV[ps], vp + (size_t)(it + 2) * 64 * 128, 128, ht);
            CP_COMMIT();
        }
        int st = it % 3;

        // ---- S = Q K^T (batched K-LDSMs per jg) ----
        float sfr[8][4];
#pragma unroll
        for (int t = 0; t < 8; t++)
#pragma unroll
            for (int e = 0; e < 4; e++) sfr[t][e] = 0.f;

#pragma unroll
        for (int jg = 0; jg < 4; jg++) {
            int jrow = (jg << 4) + ((lane >> 4) << 3) + (lane & 7);
            int jrs = jrow * 128, jrx = (jrow & 7);
            uint32_t kf[4][4];
#pragma unroll
            for (int ks = 0; ks < 4; ks++) {
                int gr = (ks << 1) + ((lane >> 3) & 1);
                LDSM4(kf[ks][0], kf[ks][1], kf[ks][2], kf[ks][3],
                      uK[st] + jrs + ((gr ^ jrx) << 4));
            }
#pragma unroll
            for (int ks = 0; ks < 4; ks++) {
                MMAF16(sfr[jg * 2],     qf[ks][0], qf[ks][1], qf[ks][2], qf[ks][3],
                       kf[ks][0], kf[ks][1]);
                MMAF16(sfr[jg * 2 + 1], qf[ks][0], qf[ks][1], qf[ks][2], qf[ks][3],
                       kf[ks][2], kf[ks][3]);
            }
        }

        // ---- max-free exp (fp16x2 MUFU); P emerges packed ----
        uint32_t p[4][4];
#pragma unroll
        for (int t = 0; t < 8; t++) {
            __half2 e01 = h2exp2(__floats2half2_rn(sfr[t][0] - CSH, sfr[t][1] - CSH));
            __half2 e23 = h2exp2(__floats2half2_rn(sfr[t][2] - CSH, sfr[t][3] - CSH));
            int ks = t >> 1, h = (t & 1) << 1;
            p[ks][h]     = *(uint32_t*)&e01;
            p[ks][h + 1] = *(uint32_t*)&e23;
        }
        // persistent row sums of P via ones-MMA (consistent with PV weights)
#pragma unroll
        for (int ks = 0; ks < 4; ks++)
            MMAF16(lfr, p[ks][0], p[ks][1], p[ks][2], p[ks][3], ONESH2, ONESH2);

        // ---- O += P V (V-LDSMs already batched per ks) ----
#pragma unroll
        for (int ks = 0; ks < 4; ks++) {
            int jrow = (ks << 4) + (lane & 7) + (((lane >> 3) & 1) << 3);
            int jrs = jrow * 128, jrx = (jrow & 7);
            uint32_t vf[4][4];
#pragma unroll
            for (int pd = 0; pd < 4; pd++) {
                int gr = (pd << 1) + (lane >> 4);
                LDSM4T(vf[pd][0], vf[pd][1], vf[pd][2], vf[pd][3],
                       uV[st] + jrs + ((gr ^ jrx) << 4));
            }
#pragma unroll
            for (int dt = 0; dt < 8; dt++) {
                int pd = dt >> 1, h = (dt & 1) << 1;
                MMAF16(ofr[dt], p[ks][0], p[ks][1], p[ks][2], p[ks][3],
                       vf[pd][h], vf[pd][h + 1]);
            }
        }
    }

    // ---- normalize + store fp16 att [b][n][256] ----
    float inv0 = 1.f / lfr[0], inv1 = 1.f / lfr[2];
    int r = lane >> 2, c2 = (lane & 3) << 1;
    int nlo = i0 + (w << 4) + r;
    size_t rowA = ((size_t)b * 4096 + nlo) * 256 + hd * 64;
    size_t rowB = rowA + (size_t)8 * 256;
#pragma unroll
    for (int dt = 0; dt < 8; dt++) {
        int d0 = (dt << 3) + c2;
        *(uint32_t*)&g_ath[rowA + d0] = packh2(ofr[dt][0] * inv0, ofr[dt][1] * inv0);
        *(uint32_t*)&g_ath[rowB + d0] = packh2(ofr[dt][2] * inv1, ofr[dt][3] * inv1);
    }
}

// ---------------------------------------------------------------------------
// Kernel 4: proj GEMM via split-W fp16 HMMA (2 passes: A*Wh + A*Wl)
// + bias + residual. A = att [n][c] tiles, B = proj_w hi/lo [o][c].
// C [n][o] -> SMEM transpose -> out[b][o][n] fp32.
// grid (4 o-tiles, 64 n-tiles, 4 b), 128 threads.
// ---------------------------------------------------------------------------
__global__ __launch_bounds__(128) void gemm_proj_hmma(
    const float* __restrict__ bias, const float* __restrict__ resid,
    float* __restrict__ out) {
    __shared__ __align__(128) char smr[24576];  // 3 stages; reused as fp32 [64][65]
    char* sAh = smr;
    char* sWh = smr + 8192;
    char* sWl = smr + 16384;
    int tid = threadIdx.x, lane = tid & 31, w = tid >> 5;
    int b = blockIdx.z, o0 = blockIdx.x << 6, n0 = blockIdx.y << 6;
    uint32_t uAh = smem_to_u32(sAh);
    uint32_t uWh = smem_to_u32(sWh), uWl = smem_to_u32(sWl);

    float cfr[8][4];
#pragma unroll
    for (int t = 0; t < 8; t++)
#pragma unroll
        for (int e = 0; e < 4; e++) cfr[t][e] = 0.f;

    for (int c0 = 0; c0 < 256; c0 += 64) {
        cpa_tile(uAh, (const char*)g_ath + (((size_t)b * 4096 + n0) * 256 + c0) * 2, 512, tid);
        cpa_tile(uWh, (const char*)g_pwh + ((size_t)o0 * 256 + c0) * 2, 512, tid);
        cpa_tile(uWl, (const char*)g_pwl + ((size_t)o0 * 256 + c0) * 2, 512, tid);
        CP_COMMIT();
        CP_WAIT(0);
        __syncthreads();

        uint32_t ah[4][4];
        {
            int row = (w << 4) + (lane & 15);
            int rs = row * 128, rx = row & 7;
#pragma unroll
            for (int ks = 0; ks < 4; ks++) {
                int gr = (ks << 1) + (lane >> 4);
                LDSM4(ah[ks][0], ah[ks][1], ah[ks][2], ah[ks][3],
                      uAh + rs + ((gr ^ rx) << 4));
            }
        }
#pragma unroll
        for (int jo = 0; jo < 4; jo++) {
            int orow = (jo << 4) + ((lane >> 4) << 3) + (lane & 7);
            int ors = orow * 128, orx = orow & 7;
            uint32_t bh4[4][4], bl4[4][4];
#pragma unroll
            for (int ks = 0; ks < 4; ks++) {
                int gr = (ks << 1) + ((lane >> 3) & 1);
                uint32_t off = ((gr ^ orx) << 4);
                LDSM4(bh4[ks][0], bh4[ks][1], bh4[ks][2], bh4[ks][3], uWh + ors + off);
                LDSM4(bl4[ks][0], bl4[ks][1], bl4[ks][2], bl4[ks][3], uWl + ors + off);
            }
#pragma unroll
            for (int ks = 0; ks < 4; ks++) {
                MMAF16(cfr[jo * 2],     ah[ks][0], ah[ks][1], ah[ks][2], ah[ks][3],
                       bh4[ks][0], bh4[ks][1]);
                MMAF16(cfr[jo * 2 + 1], ah[ks][0], ah[ks][1], ah[ks][2], ah[ks][3],
                       bh4[ks][2], bh4[ks][3]);
                MMAF16(cfr[jo * 2],     ah[ks][0], ah[ks][1], ah[ks][2], ah[ks][3],
                       bl4[ks][0], bl4[ks][1]);
                MMAF16(cfr[jo * 2 + 1], ah[ks][0], ah[ks][1], ah[ks][2], ah[ks][3],
                       bl4[ks][2], bl4[ks][3]);
            }
        }
        __syncthreads();
    }

    // ---- transpose via SMEM, add bias + residual, store fp32 ----
    float (*sT)[65] = (float(*)[65])smr;  // 64*65*4 = 16640 B <= 24576
    int r = (w << 4) + (lane >> 2), cx = (lane & 3) << 1;
#pragma unroll
    for (int jo = 0; jo < 4; jo++)
#pragma unroll
        for (int blk = 0; blk < 2; blk++) {
            int t = jo * 2 + blk;
            int d0 = (jo << 4) + (blk << 3) + cx;
            sT[r][d0]     = cfr[t][0];
            sT[r][d0 + 1] = cfr[t][1];
            sT[r + 8][d0]     = cfr[t][2];
            sT[r + 8][d0 + 1] = cfr[t][3];
        }
    __syncthreads();

    int orow = tid >> 1, nh = (tid & 1) << 5;
    int o = o0 + orow;
    float bia = bias[o];
    size_t base = ((size_t)b * 256 + o) * 4096 + n0 + nh;
#pragma unroll
    for (int i = 0; i < 32; i += 4) {
        float4 x4 = *(const float4*)&resid[base + i];
        float4 rr;
        rr.x = sT[nh + i][orow]     + bia + x4.x;
        rr.y = sT[nh + i + 1][orow] + bia + x4.y;
        rr.z = sT[nh + i + 2][orow] + bia + x4.z;
        rr.w = sT[nh + i + 3][orow] + bia + x4.w;
        *(float4*)&out[base + i] = rr;
    }
}

// ---------------------------------------------------------------------------
extern "C" void kernel_launch(void* const* d_in, const int* in_sizes, int n_in,
                              void* d_out, int out_size) {
    const float* x      = (const float*)d_in[0];
    const float* gn_w   = (const float*)d_in[1];
    const float* gn_b   = (const float*)d_in[2];
    const float* qkv_w  = (const float*)d_in[3];
    const float* qkv_b  = (const float*)d_in[4];
    const float* proj_w = (const float*)d_in[5];
    const float* proj_b = (const float*)d_in[6];
    float* out = (float*)d_out;

    gn_stats_wconv_kernel<<<1056, 256>>>(x, gn_w, gn_b, qkv_w, proj_w);
    gn_apply_kernel<<<1024, 128>>>(x);

    dim3 gq(12, 64, 4);
    gemm_qkv_hmma<<<gq, 128>>>(qkv_b);

    dim3 gf(32, 16);
    flash_mma_kernel<<<gf, 256>>>();

    dim3 gp(4, 64, 4);
    gemm_proj_hmma<<<gp, 128>>>(proj_b, x, out);
}

// round 15
// speedup vs baseline: 1.0476x; 1.0476x over previous
#include <cuda_runtime.h>
#include <cuda_fp16.h>
#include <cstdint>

// Problem: b=4, c=256, h=w=64 -> n=4096, GROUPS=8, HEADS=4, head_dim=64
// bh = b*4+head in [0,16)

// ---------------------------------------------------------------------------
// Scratch (__device__ globals; no allocation allowed)
// ---------------------------------------------------------------------------
__device__ __half g_xh[(size_t)4 * 256 * 4096];   // normalized x, fp16 [b*256+c][n]
__device__ __half g_wqh[768 * 256];               // qkv_w fp16
__device__ __half g_pwh[256 * 256];               // proj_w fp16 hi
__device__ __half g_pwl[256 * 256];               // proj_w fp16 lo
__device__ __half g_q[(size_t)16 * 4096 * 64];    // [bh][n][d], pre-scaled 0.125*log2e
__device__ __half g_k[(size_t)16 * 4096 * 64];    // [bh][n][d]
__device__ __half g_v[(size_t)16 * 4096 * 64];    // [bh][n][d]
__device__ __half g_ath[(size_t)4 * 4096 * 256];  // attention out fp16 [b][n][c]
__device__ float g_sA[1024];
__device__ float g_sB[1024];

// ---------------------------------------------------------------------------
// PTX helpers (baseline sm_80+ features only)
// ---------------------------------------------------------------------------
__device__ __forceinline__ uint32_t smem_to_u32(const void* p) {
    uint32_t a;
    asm("{ .reg .u64 t; cvta.to.shared.u64 t, %1; cvt.u32.u64 %0, t; }" : "=r"(a) : "l"(p));
    return a;
}
#define LDSM4(r0, r1, r2, r3, addr) \
    asm volatile("ldmatrix.sync.aligned.m8n8.x4.shared.b16 {%0,%1,%2,%3}, [%4];" \
        : "=r"(r0), "=r"(r1), "=r"(r2), "=r"(r3) : "r"(addr))
#define LDSM4T(r0, r1, r2, r3, addr) \
    asm volatile("ldmatrix.sync.aligned.m8n8.x4.trans.shared.b16 {%0,%1,%2,%3}, [%4];" \
        : "=r"(r0), "=r"(r1), "=r"(r2), "=r"(r3) : "r"(addr))
#define MMAF16(c, a0, a1, a2, a3, b0, b1) \
    asm volatile("mma.sync.aligned.m16n8k16.row.col.f32.f16.f16.f32 " \
        "{%0,%1,%2,%3}, {%4,%5,%6,%7}, {%8,%9}, {%0,%1,%2,%3};" \
        : "+f"((c)[0]), "+f"((c)[1]), "+f"((c)[2]), "+f"((c)[3]) \
        : "r"(a0), "r"(a1), "r"(a2), "r"(a3), "r"(b0), "r"(b1))
// fp16-accumulate HMMA: D,C packed half2 x2 (2x rate vs f32 accum)
#define MMAH16(c, a0, a1, a2, a3, b0, b1) \
    asm volatile("mma.sync.aligned.m16n8k16.row.col.f16.f16.f16.f16 " \
        "{%0,%1}, {%2,%3,%4,%5}, {%6,%7}, {%0,%1};" \
        : "+r"((c)[0]), "+r"((c)[1]) \
        : "r"(a0), "r"(a1), "r"(a2), "r"(a3), "r"(b0), "r"(b1))
#define CP_COMMIT() asm volatile("cp.async.commit_group;" ::: "memory")
#define CP_WAIT(n)  asm volatile("cp.async.wait_group %0;" :: "n"(n) : "memory")

__device__ __forceinline__ uint32_t packh2(float a, float b) {
    __half2 h = __floats2half2_rn(a, b);
    return *(uint32_t*)&h;
}

// cp.async one [64 rows][128B] tile into swizzled SMEM; 128 participating
// threads (ht in 0..127); gmem row pitch in bytes
__device__ __forceinline__ void cpa_tile(uint32_t dst, const char* src, int pitch, int ht) {
    int j = ht >> 1, g0 = (ht & 1) << 2;
    const char* s = src + (size_t)j * pitch + g0 * 16;
#pragma unroll
    for (int r = 0; r < 4; r++) {
        int g = g0 + r;
        uint32_t d = dst + j * 128 + ((g ^ (j & 7)) << 4);
        asm volatile("cp.async.cg.shared.global [%0], [%1], 16;" :: "r"(d), "l"(s + r * 16));
    }
}

// ---------------------------------------------------------------------------
// Kernel 1: GroupNorm statistics + weight conversion (merged).
// blocks [0,32): GN stats -> per-(b,c) affine; blocks [32,1056): wconv.
// ---------------------------------------------------------------------------
__global__ __launch_bounds__(256) void gn_stats_wconv_kernel(
    const float* __restrict__ x, const float* __restrict__ gw,
    const float* __restrict__ gb, const float* __restrict__ qkv_w,
    const float* __restrict__ proj_w) {
    if (blockIdx.x >= 32) {
        int i = (blockIdx.x - 32) * 256 + threadIdx.x;
        if (i < 196608) g_wqh[i] = __float2half_rn(qkv_w[i]);
        int j = i - 196608;
        if (j >= 0 && j < 65536) {
            float v = proj_w[j];
            __half h = __float2half_rn(v);
            g_pwh[j] = h;
            g_pwl[j] = __float2half_rn(v - __half2float(h));
        }
        return;
    }
    int b = blockIdx.x >> 3, g = blockIdx.x & 7;
    const float4* xp = (const float4*)(x + (size_t)(b * 256 + g * 32) * 4096);
    float s = 0.f, s2 = 0.f;
    for (int i = threadIdx.x; i < 32768; i += 256) {
        float4 v = xp[i];
        s  += v.x + v.y + v.z + v.w;
        s2 += v.x * v.x + v.y * v.y + v.z * v.z + v.w * v.w;
    }
#pragma unroll
    for (int o = 16; o; o >>= 1) {
        s  += __shfl_xor_sync(~0u, s, o);
        s2 += __shfl_xor_sync(~0u, s2, o);
    }
    __shared__ float ss[8], ss2[8], stat[2];
    int w = threadIdx.x >> 5;
    if ((threadIdx.x & 31) == 0) { ss[w] = s; ss2[w] = s2; }
    __syncthreads();
    if (threadIdx.x == 0) {
        float t = 0.f, t2 = 0.f;
        for (int k = 0; k < 8; k++) { t += ss[k]; t2 += ss2[k]; }
        float mean = t * (1.f / 131072.f);
        float var  = t2 * (1.f / 131072.f) - mean * mean;
        stat[0] = mean;
        stat[1] = rsqrtf(var + 1e-5f);
    }
    __syncthreads();
    if (threadIdx.x < 32) {
        int c = g * 32 + threadIdx.x;
        float wv = gw[c];
        g_sA[b * 256 + c] = wv * stat[1];
        g_sB[b * 256 + c] = gb[c] - stat[0] * wv * stat[1];
    }
}

// ---------------------------------------------------------------------------
// Kernel 1b: apply GN affine, write fp16 xn [b*256+c][n]
// ---------------------------------------------------------------------------
__global__ __launch_bounds__(128) void gn_apply_kernel(const float* __restrict__ x) {
    int row = blockIdx.x;
    float a = g_sA[row], sh = g_sB[row];
    const float4* xr = (const float4*)(x + (size_t)row * 4096);
    uint2* dst = (uint2*)(g_xh + (size_t)row * 4096);
    for (int i = threadIdx.x; i < 1024; i += 128) {
        float4 v = xr[i];
        uint2 p;
        p.x = packh2(fmaf(v.x, a, sh), fmaf(v.y, a, sh));
        p.y = packh2(fmaf(v.z, a, sh), fmaf(v.w, a, sh));
        dst[i] = p;
    }
}

// ---------------------------------------------------------------------------
// Kernel 2: QKV GEMM via HMMA (single-pass fp16), 2-stage cp.async pipeline.
// out[n 64][o 64] per CTA; A = xn^T (ldmatrix.trans on [c][n] tiles),
// B = qkv_w [o][c]. Epilogue: bias + (q scale) -> fp16 [bh][n][d].
// grid (12 o-tiles, 64 n-tiles, 4 b), 128 threads = 4 warps (warp: 16 n rows).
// ---------------------------------------------------------------------------
__global__ __launch_bounds__(128) void gemm_qkv_hmma(const float* __restrict__ bias) {
    __shared__ __align__(128) char sX[2][8192];  // [64 c][64 n] fp16 swizzled
    __shared__ __align__(128) char sW[2][8192];  // [64 o][64 c] fp16 swizzled
    int tid = threadIdx.x, lane = tid & 31, w = tid >> 5;
    int b = blockIdx.z, o0 = blockIdx.x << 6, n0 = blockIdx.y << 6;
    uint32_t uX[2] = {smem_to_u32(sX[0]), smem_to_u32(sX[1])};
    uint32_t uW[2] = {smem_to_u32(sW[0]), smem_to_u32(sW[1])};
    const char* xp = (const char*)g_xh + ((size_t)(b * 256) * 4096 + n0) * 2;
    const char* wp = (const char*)g_wqh + ((size_t)o0 * 256) * 2;

    float cfr[8][4];
#pragma unroll
    for (int t = 0; t < 8; t++)
#pragma unroll
        for (int e = 0; e < 4; e++) cfr[t][e] = 0.f;

    cpa_tile(uX[0], xp, 8192, tid);
    cpa_tile(uW[0], wp, 512, tid);
    CP_COMMIT();

    for (int ci = 0; ci < 4; ci++) {
        int st = ci & 1;
        if (ci < 3) {
            cpa_tile(uX[st ^ 1], xp + (size_t)(ci + 1) * 64 * 8192, 8192, tid);
            cpa_tile(uW[st ^ 1], wp + (ci + 1) * 128, 512, tid);
            CP_COMMIT();
            CP_WAIT(1);
        } else {
            CP_WAIT(0);
        }
        __syncthreads();

        // A fragments (rows = n, K = c) via trans loads, batched
        uint32_t af[4][4];
#pragma unroll
        for (int ks = 0; ks < 4; ks++) {
            int crow = (ks << 4) + ((lane >> 4) << 3) + (lane & 7);
            int g = (w << 1) + ((lane >> 3) & 1);
            LDSM4T(af[ks][0], af[ks][1], af[ks][2], af[ks][3],
                   uX[st] + crow * 128 + ((g ^ (crow & 7)) << 4));
        }
        // B fragments: batch 4 LDSMs per jo, then 8 MMAs
#pragma unroll
        for (int jo = 0; jo < 4; jo++) {
            int orow = (jo << 4) + ((lane >> 4) << 3) + (lane & 7);
            int ors = orow * 128, orx = orow & 7;
            uint32_t bf[4][4];
#pragma unroll
            for (int ks = 0; ks < 4; ks++) {
                int gr = (ks << 1) + ((lane >> 3) & 1);
                LDSM4(bf[ks][0], bf[ks][1], bf[ks][2], bf[ks][3],
                      uW[st] + ors + ((gr ^ orx) << 4));
            }
#pragma unroll
            for (int ks = 0; ks < 4; ks++) {
                MMAF16(cfr[jo * 2],     af[ks][0], af[ks][1], af[ks][2], af[ks][3],
                       bf[ks][0], bf[ks][1]);
                MMAF16(cfr[jo * 2 + 1], af[ks][0], af[ks][1], af[ks][2], af[ks][3],
                       bf[ks][2], bf[ks][3]);
            }
        }
        __syncthreads();
    }

    // epilogue: o tile = one head of one section
    int sect = o0 >> 8;                 // 0=q 1=k 2=v
    int bh = b * 4 + ((o0 >> 6) & 3);
    float scale = (sect == 0) ? 0.18033688f : 1.0f;  // 0.125 * log2(e)
    __half* dst = (sect == 0) ? g_q : ((sect == 1) ? g_k : g_v);
    int r = (w << 4) + (lane >> 2), cx = (lane & 3) << 1;
    size_t rowA = ((size_t)bh * 4096 + n0 + r) * 64;
    size_t rowB = rowA + 8 * 64;
#pragma unroll
    for (int jo = 0; jo < 4; jo++)
#pragma unroll
        for (int blk = 0; blk < 2; blk++) {
            int t = jo * 2 + blk;
            int d0 = (jo << 4) + (blk << 3) + cx;
            float b0f = bias[o0 + d0], b1f = bias[o0 + d0 + 1];
            *(uint32_t*)&dst[rowA + d0] =
                packh2((cfr[t][0] + b0f) * scale, (cfr[t][1] + b1f) * scale);
            *(uint32_t*)&dst[rowB + d0] =
                packh2((cfr[t][2] + b0f) * scale, (cfr[t][3] + b1f) * scale);
        }
}

// ---------------------------------------------------------------------------
// Kernel 3: flash attention via warp mma.sync.
// grid (32 i-tiles of 128 queries, 16 bh), 256 threads = 8 warps; warp w owns
// query rows w*16..+15. Threads 0-127 stream K, 128-255 stream V (cp.async,
// double-buffered 64-key chunks, round-13 structure).
// S phase: fp16-ACCUMULATE HMMA (2x rate), ks-outer loop -> 8 independent
// accumulator chains (reuse distance 8 MMAs). S output is half2 pairs in
// P-fragment layout: softmax = hsub2 + h2exp2 directly, zero conversions.
// Max-free softmax (fixed C=6 exp2-domain shift, cancels in O/l); l via
// persistent ones-column f32 MMA; PV in f32 accum. reg cap 128 via (256,2).
// Output: fp16 att [b][n][256].
// ---------------------------------------------------------------------------
__global__ __launch_bounds__(256, 2) void flash_mma_kernel() {
    __shared__ __align__(128) char sK[2][8192];
    __shared__ __align__(128) char sV[2][8192];
    int tid = threadIdx.x, lane = tid & 31, w = tid >> 5;
    int half = tid >> 7, ht = tid & 127;
    int bh = blockIdx.y, b = bh >> 2, hd = bh & 3;
    int i0 = blockIdx.x << 7;

    uint32_t uK[2] = {smem_to_u32(sK[0]), smem_to_u32(sK[1])};
    uint32_t uV[2] = {smem_to_u32(sV[0]), smem_to_u32(sV[1])};
    const char* qp = (const char*)g_q + ((size_t)bh * 4096 + i0) * 128;
    const char* kp = (const char*)g_k + ((size_t)bh * 4096) * 128;
    const char* vp = (const char*)g_v + ((size_t)bh * 4096) * 128;

    // ---- stage Q (128 rows): half 0 -> sK[0] rows 0-63, half 1 -> sK[1] ----
    cpa_tile(uK[half], qp + (size_t)half * 64 * 128, 128, ht);
    CP_COMMIT();
    CP_WAIT(0);
    __syncthreads();
    uint32_t qf[4][4];
    {
        int qbuf = w >> 2;
        int row = ((w << 4) & 63) + (lane & 15);
        int rs = row * 128, rx = (row & 7);
#pragma unroll
        for (int ks = 0; ks < 4; ks++) {
            int gr = (ks << 1) + (lane >> 4);
            LDSM4(qf[ks][0], qf[ks][1], qf[ks][2], qf[ks][3],
                  uK[qbuf] + rs + ((gr ^ rx) << 4));
        }
    }
    __syncthreads();  // all reads of sK done before chunk-0 prefetch

    // ---- prefetch chunk 0 (half 0: K, half 1: V) ----
    if (half == 0) cpa_tile(uK[0], kp, 128, ht);
    else           cpa_tile(uV[0], vp, 128, ht);
    CP_COMMIT();

    float ofr[8][4];
#pragma unroll
    for (int dt = 0; dt < 8; dt++)
#pragma unroll
        for (int e = 0; e < 4; e++) ofr[dt][e] = 0.f;
    float lfr[4] = {0.f, 0.f, 0.f, 0.f};
    const uint32_t ONESH2 = 0x3C003C00u;  // half2(1,1)
    const __half2 CSH2 = __floats2half2_rn(6.0f, 6.0f);  // fixed exp2 shift

    int st = 0;
    for (int j0 = 0; j0 < 4096; j0 += 64) {
        if (j0 + 64 < 4096) {
            if (half == 0) cpa_tile(uK[st ^ 1], kp + (size_t)(j0 + 64) * 128, 128, ht);
            else           cpa_tile(uV[st ^ 1], vp + (size_t)(j0 + 64) * 128, 128, ht);
            CP_COMMIT();
            CP_WAIT(1);
        } else {
            CP_WAIT(0);
        }
        __syncthreads();

        // ---- S = Q K^T, fp16 accumulators, ks-outer (8 indep chains) ----
        uint32_t sf[8][2];
#pragma unroll
        for (int t = 0; t < 8; t++) { sf[t][0] = 0u; sf[t][1] = 0u; }

#pragma unroll
        for (int ks = 0; ks < 4; ks++) {
            uint32_t kf[4][4];
#pragma unroll
            for (int jg = 0; jg < 4; jg++) {
                int jrow = (jg << 4) + ((lane >> 4) << 3) + (lane & 7);
                int gr = (ks << 1) + ((lane >> 3) & 1);
                LDSM4(kf[jg][0], kf[jg][1], kf[jg][2], kf[jg][3],
                      uK[st] + jrow * 128 + ((gr ^ (jrow & 7)) << 4));
            }
#pragma unroll
            for (int jg = 0; jg < 4; jg++) {
                MMAH16(sf[jg * 2],     qf[ks][0], qf[ks][1], qf[ks][2], qf[ks][3],
                       kf[jg][0], kf[jg][1]);
                MMAH16(sf[jg * 2 + 1], qf[ks][0], qf[ks][1], qf[ks][2], qf[ks][3],
                       kf[jg][2], kf[jg][3]);
            }
        }

        // ---- max-free exp: hsub2 + h2exp2, already in P-fragment layout ----
        uint32_t p[4][4];
#pragma unroll
        for (int t = 0; t < 8; t++) {
            __half2 e01 = h2exp2(__hsub2(*(__half2*)&sf[t][0], CSH2));
            __half2 e23 = h2exp2(__hsub2(*(__half2*)&sf[t][1], CSH2));
            int ks = t >> 1, h = (t & 1) << 1;
            p[ks][h]     = *(uint32_t*)&e01;
            p[ks][h + 1] = *(uint32_t*)&e23;
        }
        // persistent row sums of P via ones-MMA (consistent with PV weights)
#pragma unroll
        for (int ks = 0; ks < 4; ks++)
            MMAF16(lfr, p[ks][0], p[ks][1], p[ks][2], p[ks][3], ONESH2, ONESH2);

        // ---- O += P V (f32 accum; V-LDSMs batched per ks) ----
#pragma unroll
        for (int ks = 0; ks < 4; ks++) {
            int jrow = (ks << 4) + (lane & 7) + (((lane >> 3) & 1) << 3);
            int jrs = jrow * 128, jrx = (jrow & 7);
            uint32_t vf[4][4];
#pragma unroll
            for (int pd = 0; pd < 4; pd++) {
                int gr = (pd << 1) + (lane >> 4);
                LDSM4T(vf[pd][0], vf[pd][1], vf[pd][2], vf[pd][3],
                       uV[st] + jrs + ((gr ^ jrx) << 4));
            }
#pragma unroll
            for (int dt = 0; dt < 8; dt++) {
                int pd = dt >> 1, h = (dt & 1) << 1;
                MMAF16(ofr[dt], p[ks][0], p[ks][1], p[ks][2], p[ks][3],
                       vf[pd][h], vf[pd][h + 1]);
            }
        }
        __syncthreads();  // all reads of stage st done before refill
        st ^= 1;
    }

    // ---- normalize + store fp16 att [b][n][256] ----
    float inv0 = 1.f / lfr[0], inv1 = 1.f / lfr[2];
    int r = lane >> 2, c2 = (lane & 3) << 1;
    int nlo = i0 + (w << 4) + r;
    size_t rowA = ((size_t)b * 4096 + nlo) * 256 + hd * 64;
    size_t rowB = rowA + (size_t)8 * 256;
#pragma unroll
    for (int dt = 0; dt < 8; dt++) {
        int d0 = (dt << 3) + c2;
        *(uint32_t*)&g_ath[rowA + d0] = packh2(ofr[dt][0] * inv0, ofr[dt][1] * inv0);
        *(uint32_t*)&g_ath[rowB + d0] = packh2(ofr[dt][2] * inv1, ofr[dt][3] * inv1);
    }
}

// ---------------------------------------------------------------------------
// Kernel 4: proj GEMM via split-W fp16 HMMA (2 passes: A*Wh + A*Wl)
// + bias + residual. A = att [n][c] tiles, B = proj_w hi/lo [o][c].
// C [n][o] -> SMEM transpose -> out[b][o][n] fp32.
// grid (4 o-tiles, 64 n-tiles, 4 b), 128 threads.
// ---------------------------------------------------------------------------
__global__ __launch_bounds__(128) void gemm_proj_hmma(
    const float* __restrict__ bias, const float* __restrict__ resid,
    float* __restrict__ out) {
    __shared__ __align__(128) char smr[24576];  // 3 stages; reused as fp32 [64][65]
    char* sAh = smr;
    char* sWh = smr + 8192;
    char* sWl = smr + 16384;
    int tid = threadIdx.x, lane = tid & 31, w = tid >> 5;
    int b = blockIdx.z, o0 = blockIdx.x << 6, n0 = blockIdx.y << 6;
    uint32_t uAh = smem_to_u32(sAh);
    uint32_t uWh = smem_to_u32(sWh), uWl = smem_to_u32(sWl);

    float cfr[8][4];
#pragma unroll
    for (int t = 0; t < 8; t++)
#pragma unroll
        for (int e = 0; e < 4; e++) cfr[t][e] = 0.f;

    for (int c0 = 0; c0 < 256; c0 += 64) {
        cpa_tile(uAh, (const char*)g_ath + (((size_t)b * 4096 + n0) * 256 + c0) * 2, 512, tid);
        cpa_tile(uWh, (const char*)g_pwh + ((size_t)o0 * 256 + c0) * 2, 512, tid);
        cpa_tile(uWl, (const char*)g_pwl + ((size_t)o0 * 256 + c0) * 2, 512, tid);
        CP_COMMIT();
        CP_WAIT(0);
        __syncthreads();

        uint32_t ah[4][4];
        {
            int row = (w << 4) + (lane & 15);
            int rs = row * 128, rx = row & 7;
#pragma unroll
            for (int ks = 0; ks < 4; ks++) {
                int gr = (ks << 1) + (lane >> 4);
                LDSM4(ah[ks][0], ah[ks][1], ah[ks][2], ah[ks][3],
                      uAh + rs + ((gr ^ rx) << 4));
            }
        }
#pragma unroll
        for (int jo = 0; jo < 4; jo++) {
            int orow = (jo << 4) + ((lane >> 4) << 3) + (lane & 7);
            int ors = orow * 128, orx = orow & 7;
            uint32_t bh4[4][4], bl4[4][4];
#pragma unroll
            for (int ks = 0; ks < 4; ks++) {
                int gr = (ks << 1) + ((lane >> 3) & 1);
                uint32_t off = ((gr ^ orx) << 4);
                LDSM4(bh4[ks][0], bh4[ks][1], bh4[ks][2], bh4[ks][3], uWh + ors + off);
                LDSM4(bl4[ks][0], bl4[ks][1], bl4[ks][2], bl4[ks][3], uWl + ors + off);
            }
#pragma unroll
            for (int ks = 0; ks < 4; ks++) {
                MMAF16(cfr[jo * 2],     ah[ks][0], ah[ks][1], ah[ks][2], ah[ks][3],
                       bh4[ks][0], bh4[ks][1]);
                MMAF16(cfr[jo * 2 + 1], ah[ks][0], ah[ks][1], ah[ks][2], ah[ks][3],
                       bh4[ks][2], bh4[ks][3]);
                MMAF16(cfr[jo * 2],     ah[ks][0], ah[ks][1], ah[ks][2], ah[ks][3],
                       bl4[ks][0], bl4[ks][1]);
                MMAF16(cfr[jo * 2 + 1], ah[ks][0], ah[ks][1], ah[ks][2], ah[ks][3],
                       bl4[ks][2], bl4[ks][3]);
            }
        }
        __syncthreads();
    }

    // ---- transpose via SMEM, add bias + residual, store fp32 ----
    float (*sT)[65] = (float(*)[65])smr;  // 64*65*4 = 16640 B <= 24576
    int r = (w << 4) + (lane >> 2), cx = (lane & 3) << 1;
#pragma unroll
    for (int jo = 0; jo < 4; jo++)
#pragma unroll
        for (int blk = 0; blk < 2; blk++) {
            int t = jo * 2 + blk;
            int d0 = (jo << 4) + (blk << 3) + cx;
            sT[r][d0]     = cfr[t][0];
            sT[r][d0 + 1] = cfr[t][1];
            sT[r + 8][d0]     = cfr[t][2];
            sT[r + 8][d0 + 1] = cfr[t][3];
        }
    __syncthreads();

    int orow = tid >> 1, nh = (tid & 1) << 5;
    int o = o0 + orow;
    float bia = bias[o];
    size_t base = ((size_t)b * 256 + o) * 4096 + n0 + nh;
#pragma unroll
    for (int i = 0; i < 32; i += 4) {
        float4 x4 = *(const float4*)&resid[base + i];
        float4 rr;
        rr.x = sT[nh + i][orow]     + bia + x4.x;
        rr.y = sT[nh + i + 1][orow] + bia + x4.y;
        rr.z = sT[nh + i + 2][orow] + bia + x4.z;
        rr.w = sT[nh + i + 3][orow] + bia + x4.w;
        *(float4*)&out[base + i] = rr;
    }
}

// ---------------------------------------------------------------------------
extern "C" void kernel_launch(void* const* d_in, const int* in_sizes, int n_in,
                              void* d_out, int out_size) {
    const float* x      = (const float*)d_in[0];
    const float* gn_w   = (const float*)d_in[1];
    const float* gn_b   = (const float*)d_in[2];
    const float* qkv_w  = (const float*)d_in[3];
    const float* qkv_b  = (const float*)d_in[4];
    const float* proj_w = (const float*)d_in[5];
    const float* proj_b = (const float*)d_in[6];
    float* out = (float*)d_out;

    gn_stats_wconv_kernel<<<1056, 256>>>(x, gn_w, gn_b, qkv_w, proj_w);
    gn_apply_kernel<<<1024, 128>>>(x);

    dim3 gq(12, 64, 4);
    gemm_qkv_hmma<<<gq, 128>>>(qkv_b);

    dim3 gf(32, 16);
    flash_mma_kernel<<<gf, 256>>>();

    dim3 gp(4, 64, 4);
    gemm_proj_hmma<<<gp, 128>>>(proj_b, x, out);
}

// round 16
// speedup vs baseline: 1.1243x; 1.0732x over previous
#include <cuda_runtime.h>
#include <cuda_fp16.h>
#include <cstdint>

// Problem: b=4, c=256, h=w=64 -> n=4096, GROUPS=8, HEADS=4, head_dim=64
// bh = b*4+head in [0,16)

// ---------------------------------------------------------------------------
// Scratch (__device__ globals; no allocation allowed)
// ---------------------------------------------------------------------------
__device__ __half g_xh[(size_t)4 * 256 * 4096];   // normalized x, fp16 [b*256+c][n]
__device__ __half g_wqh[768 * 256];               // qkv_w fp16
__device__ __half g_pwh[256 * 256];               // proj_w fp16 hi
__device__ __half g_pwl[256 * 256];               // proj_w fp16 lo
__device__ __half g_q[(size_t)16 * 4096 * 64];    // [bh][n][d], pre-scaled 0.125*log2e
__device__ __half g_k[(size_t)16 * 4096 * 64];    // [bh][n][d]
__device__ __half g_v[(size_t)16 * 4096 * 64];    // [bh][n][d]
__device__ __half g_ath[(size_t)4 * 4096 * 256];  // attention out fp16 [b][n][c]
__device__ float g_sA[1024];
__device__ float g_sB[1024];

// ---------------------------------------------------------------------------
// PTX helpers (baseline sm_80+ features only)
// ---------------------------------------------------------------------------
__device__ __forceinline__ uint32_t smem_to_u32(const void* p) {
    uint32_t a;
    asm("{ .reg .u64 t; cvta.to.shared.u64 t, %1; cvt.u32.u64 %0, t; }" : "=r"(a) : "l"(p));
    return a;
}
#define LDSM4(r0, r1, r2, r3, addr) \
    asm volatile("ldmatrix.sync.aligned.m8n8.x4.shared.b16 {%0,%1,%2,%3}, [%4];" \
        : "=r"(r0), "=r"(r1), "=r"(r2), "=r"(r3) : "r"(addr))
#define LDSM4T(r0, r1, r2, r3, addr) \
    asm volatile("ldmatrix.sync.aligned.m8n8.x4.trans.shared.b16 {%0,%1,%2,%3}, [%4];" \
        : "=r"(r0), "=r"(r1), "=r"(r2), "=r"(r3) : "r"(addr))
#define MMAF16(c, a0, a1, a2, a3, b0, b1) \
    asm volatile("mma.sync.aligned.m16n8k16.row.col.f32.f16.f16.f32 " \
        "{%0,%1,%2,%3}, {%4,%5,%6,%7}, {%8,%9}, {%0,%1,%2,%3};" \
        : "+f"((c)[0]), "+f"((c)[1]), "+f"((c)[2]), "+f"((c)[3]) \
        : "r"(a0), "r"(a1), "r"(a2), "r"(a3), "r"(b0), "r"(b1))
// fp16-accumulate HMMA: D,C packed half2 x2 (half the accumulator regs)
#define MMAH16(c, a0, a1, a2, a3, b0, b1) \
    asm volatile("mma.sync.aligned.m16n8k16.row.col.f16.f16.f16.f16 " \
        "{%0,%1}, {%2,%3,%4,%5}, {%6,%7}, {%0,%1};" \
        : "+r"((c)[0]), "+r"((c)[1]) \
        : "r"(a0), "r"(a1), "r"(a2), "r"(a3), "r"(b0), "r"(b1))
#define CP_COMMIT() asm volatile("cp.async.commit_group;" ::: "memory")
#define CP_WAIT(n)  asm volatile("cp.async.wait_group %0;" :: "n"(n) : "memory")

__device__ __forceinline__ uint32_t packh2(float a, float b) {
    __half2 h = __floats2half2_rn(a, b);
    return *(uint32_t*)&h;
}

// cp.async one [64 rows][128B] tile into swizzled SMEM; 128 participating
// threads (ht in 0..127); gmem row pitch in bytes
__device__ __forceinline__ void cpa_tile(uint32_t dst, const char* src, int pitch, int ht) {
    int j = ht >> 1, g0 = (ht & 1) << 2;
    const char* s = src + (size_t)j * pitch + g0 * 16;
#pragma unroll
    for (int r = 0; r < 4; r++) {
        int g = g0 + r;
        uint32_t d = dst + j * 128 + ((g ^ (j & 7)) << 4);
        asm volatile("cp.async.cg.shared.global [%0], [%1], 16;" :: "r"(d), "l"(s + r * 16));
    }
}

// ---------------------------------------------------------------------------
// Kernel 1: GroupNorm statistics + weight conversion (merged).
// blocks [0,32): GN stats -> per-(b,c) affine; blocks [32,1056): wconv.
// ---------------------------------------------------------------------------
__global__ __launch_bounds__(256) void gn_stats_wconv_kernel(
    const float* __restrict__ x, const float* __restrict__ gw,
    const float* __restrict__ gb, const float* __restrict__ qkv_w,
    const float* __restrict__ proj_w) {
    if (blockIdx.x >= 32) {
        int i = (blockIdx.x - 32) * 256 + threadIdx.x;
        if (i < 196608) g_wqh[i] = __float2half_rn(qkv_w[i]);
        int j = i - 196608;
        if (j >= 0 && j < 65536) {
            float v = proj_w[j];
            __half h = __float2half_rn(v);
            g_pwh[j] = h;
            g_pwl[j] = __float2half_rn(v - __half2float(h));
        }
        return;
    }
    int b = blockIdx.x >> 3, g = blockIdx.x & 7;
    const float4* xp = (const float4*)(x + (size_t)(b * 256 + g * 32) * 4096);
    float s = 0.f, s2 = 0.f;
    for (int i = threadIdx.x; i < 32768; i += 256) {
        float4 v = xp[i];
        s  += v.x + v.y + v.z + v.w;
        s2 += v.x * v.x + v.y * v.y + v.z * v.z + v.w * v.w;
    }
#pragma unroll
    for (int o = 16; o; o >>= 1) {
        s  += __shfl_xor_sync(~0u, s, o);
        s2 += __shfl_xor_sync(~0u, s2, o);
    }
    __shared__ float ss[8], ss2[8], stat[2];
    int w = threadIdx.x >> 5;
    if ((threadIdx.x & 31) == 0) { ss[w] = s; ss2[w] = s2; }
    __syncthreads();
    if (threadIdx.x == 0) {
        float t = 0.f, t2 = 0.f;
        for (int k = 0; k < 8; k++) { t += ss[k]; t2 += ss2[k]; }
        float mean = t * (1.f / 131072.f);
        float var  = t2 * (1.f / 131072.f) - mean * mean;
        stat[0] = mean;
        stat[1] = rsqrtf(var + 1e-5f);
    }
    __syncthreads();
    if (threadIdx.x < 32) {
        int c = g * 32 + threadIdx.x;
        float wv = gw[c];
        g_sA[b * 256 + c] = wv * stat[1];
        g_sB[b * 256 + c] = gb[c] - stat[0] * wv * stat[1];
    }
}

// ---------------------------------------------------------------------------
// Kernel 1b: apply GN affine, write fp16 xn [b*256+c][n]
// ---------------------------------------------------------------------------
__global__ __launch_bounds__(128) void gn_apply_kernel(const float* __restrict__ x) {
    int row = blockIdx.x;
    float a = g_sA[row], sh = g_sB[row];
    const float4* xr = (const float4*)(x + (size_t)row * 4096);
    uint2* dst = (uint2*)(g_xh + (size_t)row * 4096);
    for (int i = threadIdx.x; i < 1024; i += 128) {
        float4 v = xr[i];
        uint2 p;
        p.x = packh2(fmaf(v.x, a, sh), fmaf(v.y, a, sh));
        p.y = packh2(fmaf(v.z, a, sh), fmaf(v.w, a, sh));
        dst[i] = p;
    }
}

// ---------------------------------------------------------------------------
// Kernel 2: QKV GEMM via HMMA (single-pass fp16), 2-stage cp.async pipeline.
// out[n 64][o 64] per CTA; A = xn^T (ldmatrix.trans on [c][n] tiles),
// B = qkv_w [o][c]. Epilogue: bias + (q scale) -> fp16 [bh][n][d].
// grid (12 o-tiles, 64 n-tiles, 4 b), 128 threads = 4 warps (warp: 16 n rows).
// ---------------------------------------------------------------------------
__global__ __launch_bounds__(128) void gemm_qkv_hmma(const float* __restrict__ bias) {
    __shared__ __align__(128) char sX[2][8192];  // [64 c][64 n] fp16 swizzled
    __shared__ __align__(128) char sW[2][8192];  // [64 o][64 c] fp16 swizzled
    int tid = threadIdx.x, lane = tid & 31, w = tid >> 5;
    int b = blockIdx.z, o0 = blockIdx.x << 6, n0 = blockIdx.y << 6;
    uint32_t uX[2] = {smem_to_u32(sX[0]), smem_to_u32(sX[1])};
    uint32_t uW[2] = {smem_to_u32(sW[0]), smem_to_u32(sW[1])};
    const char* xp = (const char*)g_xh + ((size_t)(b * 256) * 4096 + n0) * 2;
    const char* wp = (const char*)g_wqh + ((size_t)o0 * 256) * 2;

    float cfr[8][4];
#pragma unroll
    for (int t = 0; t < 8; t++)
#pragma unroll
        for (int e = 0; e < 4; e++) cfr[t][e] = 0.f;

    cpa_tile(uX[0], xp, 8192, tid);
    cpa_tile(uW[0], wp, 512, tid);
    CP_COMMIT();

    for (int ci = 0; ci < 4; ci++) {
        int st = ci & 1;
        if (ci < 3) {
            cpa_tile(uX[st ^ 1], xp + (size_t)(ci + 1) * 64 * 8192, 8192, tid);
            cpa_tile(uW[st ^ 1], wp + (ci + 1) * 128, 512, tid);
            CP_COMMIT();
            CP_WAIT(1);
        } else {
            CP_WAIT(0);
        }
        __syncthreads();

        // A fragments (rows = n, K = c) via trans loads, batched
        uint32_t af[4][4];
#pragma unroll
        for (int ks = 0; ks < 4; ks++) {
            int crow = (ks << 4) + ((lane >> 4) << 3) + (lane & 7);
            int g = (w << 1) + ((lane >> 3) & 1);
            LDSM4T(af[ks][0], af[ks][1], af[ks][2], af[ks][3],
                   uX[st] + crow * 128 + ((g ^ (crow & 7)) << 4));
        }
        // B fragments: batch 4 LDSMs per jo, then 8 MMAs
#pragma unroll
        for (int jo = 0; jo < 4; jo++) {
            int orow = (jo << 4) + ((lane >> 4) << 3) + (lane & 7);
            int ors = orow * 128, orx = orow & 7;
            uint32_t bf[4][4];
#pragma unroll
            for (int ks = 0; ks < 4; ks++) {
                int gr = (ks << 1) + ((lane >> 3) & 1);
                LDSM4(bf[ks][0], bf[ks][1], bf[ks][2], bf[ks][3],
                      uW[st] + ors + ((gr ^ orx) << 4));
            }
#pragma unroll
            for (int ks = 0; ks < 4; ks++) {
                MMAF16(cfr[jo * 2],     af[ks][0], af[ks][1], af[ks][2], af[ks][3],
                       bf[ks][0], bf[ks][1]);
                MMAF16(cfr[jo * 2 + 1], af[ks][0], af[ks][1], af[ks][2], af[ks][3],
                       bf[ks][2], bf[ks][3]);
            }
        }
        __syncthreads();
    }

    // epilogue: o tile = one head of one section
    int sect = o0 >> 8;                 // 0=q 1=k 2=v
    int bh = b * 4 + ((o0 >> 6) & 3);
    float scale = (sect == 0) ? 0.18033688f : 1.0f;  // 0.125 * log2(e)
    __half* dst = (sect == 0) ? g_q : ((sect == 1) ? g_k : g_v);
    int r = (w << 4) + (lane >> 2), cx = (lane & 3) << 1;
    size_t rowA = ((size_t)bh * 4096 + n0 + r) * 64;
    size_t rowB = rowA + 8 * 64;
#pragma unroll
    for (int jo = 0; jo < 4; jo++)
#pragma unroll
        for (int blk = 0; blk < 2; blk++) {
            int t = jo * 2 + blk;
            int d0 = (jo << 4) + (blk << 3) + cx;
            float b0f = bias[o0 + d0], b1f = bias[o0 + d0 + 1];
            *(uint32_t*)&dst[rowA + d0] =
                packh2((cfr[t][0] + b0f) * scale, (cfr[t][1] + b1f) * scale);
            *(uint32_t*)&dst[rowB + d0] =
                packh2((cfr[t][2] + b0f) * scale, (cfr[t][3] + b1f) * scale);
        }
}

// ---------------------------------------------------------------------------
// Kernel 3: flash attention via warp mma.sync.
// grid (32 i-tiles of 128 queries, 16 bh), 256 threads = 8 warps; warp w owns
// query rows w*16..+15. Threads 0-127 stream K, 128-255 stream V.
// 4-stage cp.async ring, 2-CHUNK INTERLEAVED main loop: S(2j) and S(2j+1)
// issued back-to-back (16 indep fp16-acc chains), so softmax(2j)'s MUFU
// latency is covered by chunk 2j+1's queued tensor work. 1 barrier/chunk.
// Max-free softmax (fixed C=6 exp2-domain shift, cancels in O/l); l via
// persistent ones-column f32 MMA; PV f32 accum. reg cap 128 via (256,2).
// Dynamic SMEM 64 KB (4x8KB K + 4x8KB V). Output: fp16 att [b][n][256].
// ---------------------------------------------------------------------------
__global__ __launch_bounds__(256, 2) void flash_mma_kernel() {
    extern __shared__ __align__(128) char smf[];
    int tid = threadIdx.x, lane = tid & 31, w = tid >> 5;
    int half = tid >> 7, ht = tid & 127;
    int bh = blockIdx.y, b = bh >> 2, hd = bh & 3;
    int i0 = blockIdx.x << 7;

    uint32_t uKb = smem_to_u32(smf);          // 4 stages x 8192
    uint32_t uVb = uKb + 32768;               // 4 stages x 8192
    const char* qp = (const char*)g_q + ((size_t)bh * 4096 + i0) * 128;
    const char* kp = (const char*)g_k + ((size_t)bh * 4096) * 128;
    const char* vp = (const char*)g_v + ((size_t)bh * 4096) * 128;

    // ---- stage Q (128 rows) into K-stages 0,1 ----
    cpa_tile(uKb + (half << 13), qp + (size_t)half * 8192, 128, ht);
    CP_COMMIT();
    CP_WAIT(0);
    __syncthreads();
    uint32_t qf[4][4];
    {
        int qbuf = w >> 2;
        int row = ((w << 4) & 63) + (lane & 15);
        int rs = row * 128, rx = (row & 7);
#pragma unroll
        for (int ks = 0; ks < 4; ks++) {
            int gr = (ks << 1) + (lane >> 4);
            LDSM4(qf[ks][0], qf[ks][1], qf[ks][2], qf[ks][3],
                  uKb + (qbuf << 13) + rs + ((gr ^ rx) << 4));
        }
    }
    __syncthreads();  // all reads of Q staging done before chunk prefetch

    // ---- prefetch chunks 0..3 into stages 0..3 (half 0: K, half 1: V) ----
#pragma unroll
    for (int c = 0; c < 4; c++) {
        if (half == 0) cpa_tile(uKb + (c << 13), kp + (size_t)c * 8192, 128, ht);
        else           cpa_tile(uVb + (c << 13), vp + (size_t)c * 8192, 128, ht);
        CP_COMMIT();
    }

    float ofr[8][4];
#pragma unroll
    for (int dt = 0; dt < 8; dt++)
#pragma unroll
        for (int e = 0; e < 4; e++) ofr[dt][e] = 0.f;
    float lfr[4] = {0.f, 0.f, 0.f, 0.f};
    const uint32_t ONESH2 = 0x3C003C00u;  // half2(1,1)
    const __half2 CSH2 = __floats2half2_rn(6.0f, 6.0f);  // fixed exp2 shift

    for (int jp = 0; jp < 32; jp++) {
        if (jp < 31) CP_WAIT(2);   // pair jp complete; pair jp+1 in flight
        else         CP_WAIT(0);
        __syncthreads();
        uint32_t K0 = uKb + (((jp * 2)     & 3) << 13);
        uint32_t K1 = uKb + (((jp * 2 + 1) & 3) << 13);
        uint32_t V0 = uVb + (((jp * 2)     & 3) << 13);
        uint32_t V1 = uVb + (((jp * 2 + 1) & 3) << 13);

        // ---- S for BOTH chunks back-to-back (16 independent fp16-acc chains)
        uint32_t sf0[8][2], sf1[8][2];
#pragma unroll
        for (int t = 0; t < 8; t++) {
            sf0[t][0] = sf0[t][1] = 0u;
            sf1[t][0] = sf1[t][1] = 0u;
        }
#pragma unroll
        for (int ks = 0; ks < 4; ks++) {
            uint32_t kf[4][4];
#pragma unroll
            for (int jg = 0; jg < 4; jg++) {
                int jrow = (jg << 4) + ((lane >> 4) << 3) + (lane & 7);
                int gr = (ks << 1) + ((lane >> 3) & 1);
                LDSM4(kf[jg][0], kf[jg][1], kf[jg][2], kf[jg][3],
                      K0 + jrow * 128 + ((gr ^ (jrow & 7)) << 4));
            }
#pragma unroll
            for (int jg = 0; jg < 4; jg++) {
                MMAH16(sf0[jg * 2],     qf[ks][0], qf[ks][1], qf[ks][2], qf[ks][3],
                       kf[jg][0], kf[jg][1]);
                MMAH16(sf0[jg * 2 + 1], qf[ks][0], qf[ks][1], qf[ks][2], qf[ks][3],
                       kf[jg][2], kf[jg][3]);
            }
        }
#pragma unroll
        for (int ks = 0; ks < 4; ks++) {
            uint32_t kf[4][4];
#pragma unroll
            for (int jg = 0; jg < 4; jg++) {
                int jrow = (jg << 4) + ((lane >> 4) << 3) + (lane & 7);
                int gr = (ks << 1) + ((lane >> 3) & 1);
                LDSM4(kf[jg][0], kf[jg][1], kf[jg][2], kf[jg][3],
                      K1 + jrow * 128 + ((gr ^ (jrow & 7)) << 4));
            }
#pragma unroll
            for (int jg = 0; jg < 4; jg++) {
                MMAH16(sf1[jg * 2],     qf[ks][0], qf[ks][1], qf[ks][2], qf[ks][3],
                       kf[jg][0], kf[jg][1]);
                MMAH16(sf1[jg * 2 + 1], qf[ks][0], qf[ks][1], qf[ks][2], qf[ks][3],
                       kf[jg][2], kf[jg][3]);
            }
        }

        // ---- chunk 2jp: softmax + l + PV (S(2jp+1) drains on tensor pipe) --
        {
            uint32_t p[4][4];
#pragma unroll
            for (int t = 0; t < 8; t++) {
                __half2 e01 = h2exp2(__hsub2(*(__half2*)&sf0[t][0], CSH2));
                __half2 e23 = h2exp2(__hsub2(*(__half2*)&sf0[t][1], CSH2));
                int ks = t >> 1, h = (t & 1) << 1;
                p[ks][h]     = *(uint32_t*)&e01;
                p[ks][h + 1] = *(uint32_t*)&e23;
            }
#pragma unroll
            for (int ks = 0; ks < 4; ks++)
                MMAF16(lfr, p[ks][0], p[ks][1], p[ks][2], p[ks][3], ONESH2, ONESH2);
#pragma unroll
            for (int ks = 0; ks < 4; ks++) {
                int jrow = (ks << 4) + (lane & 7) + (((lane >> 3) & 1) << 3);
                int jrs = jrow * 128, jrx = (jrow & 7);
                uint32_t vf[4][4];
#pragma unroll
                for (int pd = 0; pd < 4; pd++) {
                    int gr = (pd << 1) + (lane >> 4);
                    LDSM4T(vf[pd][0], vf[pd][1], vf[pd][2], vf[pd][3],
                           V0 + jrs + ((gr ^ jrx) << 4));
                }
#pragma unroll
                for (int dt = 0; dt < 8; dt++) {
                    int pd = dt >> 1, h = (dt & 1) << 1;
                    MMAF16(ofr[dt], p[ks][0], p[ks][1], p[ks][2], p[ks][3],
                           vf[pd][h], vf[pd][h + 1]);
                }
            }
        }
        // ---- chunk 2jp+1: softmax + l + PV ----
        {
            uint32_t p[4][4];
#pragma unroll
            for (int t = 0; t < 8; t++) {
                __half2 e01 = h2exp2(__hsub2(*(__half2*)&sf1[t][0], CSH2));
                __half2 e23 = h2exp2(__hsub2(*(__half2*)&sf1[t][1], CSH2));
                int ks = t >> 1, h = (t & 1) << 1;
                p[ks][h]     = *(uint32_t*)&e01;
                p[ks][h + 1] = *(uint32_t*)&e23;
            }
#pragma unroll
            for (int ks = 0; ks < 4; ks++)
                MMAF16(lfr, p[ks][0], p[ks][1], p[ks][2], p[ks][3], ONESH2, ONESH2);
#pragma unroll
            for (int ks = 0; ks < 4; ks++) {
                int jrow = (ks << 4) + (lane & 7) + (((lane >> 3) & 1) << 3);
                int jrs = jrow * 128, jrx = (jrow & 7);
                uint32_t vf[4][4];
#pragma unroll
                for (int pd = 0; pd < 4; pd++) {
                    int gr = (pd << 1) + (lane >> 4);
                    LDSM4T(vf[pd][0], vf[pd][1], vf[pd][2], vf[pd][3],
                           V1 + jrs + ((gr ^ jrx) << 4));
                }
#pragma unroll
                for (int dt = 0; dt < 8; dt++) {
                    int pd = dt >> 1, h = (dt & 1) << 1;
                    MMAF16(ofr[dt], p[ks][0], p[ks][1], p[ks][2], p[ks][3],
                           vf[pd][h], vf[pd][h + 1]);
                }
            }
        }
        __syncthreads();  // readers done before refilling these stages
        if (jp < 30) {
            int c0 = jp * 2 + 4;
#pragma unroll
            for (int c = 0; c < 2; c++) {
                int cc = c0 + c;
                if (half == 0) cpa_tile(uKb + ((cc & 3) << 13), kp + (size_t)cc * 8192, 128, ht);
                else           cpa_tile(uVb + ((cc & 3) << 13), vp + (size_t)cc * 8192, 128, ht);
                CP_COMMIT();
            }
        }
    }

    // ---- normalize + store fp16 att [b][n][256] ----
    float inv0 = 1.f / lfr[0], inv1 = 1.f / lfr[2];
    int r = lane >> 2, c2 = (lane & 3) << 1;
    int nlo = i0 + (w << 4) + r;
    size_t rowA = ((size_t)b * 4096 + nlo) * 256 + hd * 64;
    size_t rowB = rowA + (size_t)8 * 256;
#pragma unroll
    for (int dt = 0; dt < 8; dt++) {
        int d0 = (dt << 3) + c2;
        *(uint32_t*)&g_ath[rowA + d0] = packh2(ofr[dt][0] * inv0, ofr[dt][1] * inv0);
        *(uint32_t*)&g_ath[rowB + d0] = packh2(ofr[dt][2] * inv1, ofr[dt][3] * inv1);
    }
}

// ---------------------------------------------------------------------------
// Kernel 4: proj GEMM via split-W fp16 HMMA (2 passes: A*Wh + A*Wl)
// + bias + residual. A = att [n][c] tiles, B = proj_w hi/lo [o][c].
// C [n][o] -> SMEM transpose -> out[b][o][n] fp32.
// grid (4 o-tiles, 64 n-tiles, 4 b), 128 threads.
// ---------------------------------------------------------------------------
__global__ __launch_bounds__(128) void gemm_proj_hmma(
    const float* __restrict__ bias, const float* __restrict__ resid,
    float* __restrict__ out) {
    __shared__ __align__(128) char smr[24576];  // 3 stages; reused as fp32 [64][65]
    char* sAh = smr;
    char* sWh = smr + 8192;
    char* sWl = smr + 16384;
    int tid = threadIdx.x, lane = tid & 31, w = tid >> 5;
    int b = blockIdx.z, o0 = blockIdx.x << 6, n0 = blockIdx.y << 6;
    uint32_t uAh = smem_to_u32(sAh);
    uint32_t uWh = smem_to_u32(sWh), uWl = smem_to_u32(sWl);

    float cfr[8][4];
#pragma unroll
    for (int t = 0; t < 8; t++)
#pragma unroll
        for (int e = 0; e < 4; e++) cfr[t][e] = 0.f;

    for (int c0 = 0; c0 < 256; c0 += 64) {
        cpa_tile(uAh, (const char*)g_ath + (((size_t)b * 4096 + n0) * 256 + c0) * 2, 512, tid);
        cpa_tile(uWh, (const char*)g_pwh + ((size_t)o0 * 256 + c0) * 2, 512, tid);
        cpa_tile(uWl, (const char*)g_pwl + ((size_t)o0 * 256 + c0) * 2, 512, tid);
        CP_COMMIT();
        CP_WAIT(0);
        __syncthreads();

        uint32_t ah[4][4];
        {
            int row = (w << 4) + (lane & 15);
            int rs = row * 128, rx = row & 7;
#pragma unroll
            for (int ks = 0; ks < 4; ks++) {
                int gr = (ks << 1) + (lane >> 4);
                LDSM4(ah[ks][0], ah[ks][1], ah[ks][2], ah[ks][3],
                      uAh + rs + ((gr ^ rx) << 4));
            }
        }
#pragma unroll
        for (int jo = 0; jo < 4; jo++) {
            int orow = (jo << 4) + ((lane >> 4) << 3) + (lane & 7);
            int ors = orow * 128, orx = orow & 7;
            uint32_t bh4[4][4], bl4[4][4];
#pragma unroll
            for (int ks = 0; ks < 4; ks++) {
                int gr = (ks << 1) + ((lane >> 3) & 1);
                uint32_t off = ((gr ^ orx) << 4);
                LDSM4(bh4[ks][0], bh4[ks][1], bh4[ks][2], bh4[ks][3], uWh + ors + off);
                LDSM4(bl4[ks][0], bl4[ks][1], bl4[ks][2], bl4[ks][3], uWl + ors + off);
            }
#pragma unroll
            for (int ks = 0; ks < 4; ks++) {
                MMAF16(cfr[jo * 2],     ah[ks][0], ah[ks][1], ah[ks][2], ah[ks][3],
                       bh4[ks][0], bh4[ks][1]);
                MMAF16(cfr[jo * 2 + 1], ah[ks][0], ah[ks][1], ah[ks][2], ah[ks][3],
                       bh4[ks][2], bh4[ks][3]);
                MMAF16(cfr[jo * 2],     ah[ks][0], ah[ks][1], ah[ks][2], ah[ks][3],
                       bl4[ks][0], bl4[ks][1]);
                MMAF16(cfr[jo * 2 + 1], ah[ks][0], ah[ks][1], ah[ks][2], ah[ks][3],
                       bl4[ks][2], bl4[ks][3]);
            }
        }
        __syncthreads();
    }

    // ---- transpose via SMEM, add bias + residual, store fp32 ----
    float (*sT)[65] = (float(*)[65])smr;  // 64*65*4 = 16640 B <= 24576
    int r = (w << 4) + (lane >> 2), cx = (lane & 3) << 1;
#pragma unroll
    for (int jo = 0; jo < 4; jo++)
#pragma unroll
        for (int blk = 0; blk < 2; blk++) {
            int t = jo * 2 + blk;
            int d0 = (jo << 4) + (blk << 3) + cx;
            sT[r][d0]     = cfr[t][0];
            sT[r][d0 + 1] = cfr[t][1];
            sT[r + 8][d0]     = cfr[t][2];
            sT[r + 8][d0 + 1] = cfr[t][3];
        }
    __syncthreads();

    int orow = tid >> 1, nh = (tid & 1) << 5;
    int o = o0 + orow;
    float bia = bias[o];
    size_t base = ((size_t)b * 256 + o) * 4096 + n0 + nh;
#pragma unroll
    for (int i = 0; i < 32; i += 4) {
        float4 x4 = *(const float4*)&resid[base + i];
        float4 rr;
        rr.x = sT[nh + i][orow]     + bia + x4.x;
        rr.y = sT[nh + i + 1][orow] + bia + x4.y;
        rr.z = sT[nh + i + 2][orow] + bia + x4.z;
        rr.w = sT[nh + i + 3][orow] + bia + x4.w;
        *(float4*)&out[base + i] = rr;
    }
}

// ---------------------------------------------------------------------------
extern "C" void kernel_launch(void* const* d_in, const int* in_sizes, int n_in,
                              void* d_out, int out_size) {
    const float* x      = (const float*)d_in[0];
    const float* gn_w   = (const float*)d_in[1];
    const float* gn_b   = (const float*)d_in[2];
    const float* qkv_w  = (const float*)d_in[3];
    const float* qkv_b  = (const float*)d_in[4];
    const float* proj_w = (const float*)d_in[5];
    const float* proj_b = (const float*)d_in[6];
    float* out = (float*)d_out;

    static bool attr_set = false;
    if (!attr_set) {
        cudaFuncSetAttribute(flash_mma_kernel,
                             cudaFuncAttributeMaxDynamicSharedMemorySize, 65536);
        attr_set = true;
    }

    gn_stats_wconv_kernel<<<1056, 256>>>(x, gn_w, gn_b, qkv_w, proj_w);
    gn_apply_kernel<<<1024, 128>>>(x);

    dim3 gq(12, 64, 4);
    gemm_qkv_hmma<<<gq, 128>>>(qkv_b);

    dim3 gf(32, 16);
    flash_mma_kernel<<<gf, 256, 65536>>>();

    dim3 gp(4, 64, 4);
    gemm_proj_hmma<<<gp, 128>>>(proj_b, x, out);
}